// round 6
// baseline (speedup 1.0000x reference)
#include <cuda_runtime.h>

// Scratch for the extracted diagonal (allocation-free: __device__ global).
__device__ float g_diag[4096];

// Kernel A: pull diag(W) out of the dense [4096,4096] matrix.
__global__ void extract_diag_kernel(const float* __restrict__ W) {
    int j = blockIdx.x * blockDim.x + threadIdx.x;
    if (j < 4096) {
        g_diag[j] = __ldg(&W[(size_t)j * 4097u]);
    }
}

// 256-bit global load (sm_100a+/sm_103a, PTX ISA 8.8). Non-volatile so the
// compiler can batch independent loads (MLP). .cs = streaming, evict-first.
__device__ __forceinline__ void ldg256_cs(const float* p, float* r) {
    asm("ld.global.cs.v8.f32 {%0,%1,%2,%3,%4,%5,%6,%7}, [%8];"
        : "=f"(r[0]), "=f"(r[1]), "=f"(r[2]), "=f"(r[3]),
          "=f"(r[4]), "=f"(r[5]), "=f"(r[6]), "=f"(r[7])
        : "l"(p));
}

// 256-bit global store, streaming.
__device__ __forceinline__ void stg256_cs(float* p, const float* r) {
    asm volatile("st.global.cs.v8.f32 [%0], {%1,%2,%3,%4,%5,%6,%7,%8};"
        :: "l"(p),
           "f"(r[0]), "f"(r[1]), "f"(r[2]), "f"(r[3]),
           "f"(r[4]), "f"(r[5]), "f"(r[6]), "f"(r[7])
        : "memory");
}

// Kernel B: y = x * diag (columnwise). 4 linear streams, 32B accesses.
// Total 33,554,432 floats = 4,194,304 v8; QV8 = total/4 = 1,048,576.
// 512 v8 per row; QV8 % 512 == 0 so all 4 streams share one diag v8.
#define QV8 1048576u

__global__ void diag_scale_kernel(const float* __restrict__ x,
                                  float* __restrict__ y) {
    const unsigned int i = blockIdx.x * blockDim.x + threadIdx.x;  // < QV8
    const unsigned int col8 = i & 511u;  // v8 column within the row

    const float4* d4 = reinterpret_cast<const float4*>(g_diag);
    const float4 dlo = __ldg(&d4[2u * col8]);
    const float4 dhi = __ldg(&d4[2u * col8 + 1u]);
    const float dv[8] = {dlo.x, dlo.y, dlo.z, dlo.w,
                         dhi.x, dhi.y, dhi.z, dhi.w};

    float a[8], b[8], c[8], e[8];
    ldg256_cs(x + (size_t)i * 8u,               a);
    ldg256_cs(x + ((size_t)i + QV8) * 8u,       b);
    ldg256_cs(x + ((size_t)i + 2u * QV8) * 8u,  c);
    ldg256_cs(x + ((size_t)i + 3u * QV8) * 8u,  e);

    #pragma unroll
    for (int k = 0; k < 8; k++) {
        a[k] *= dv[k];
        b[k] *= dv[k];
        c[k] *= dv[k];
        e[k] *= dv[k];
    }

    stg256_cs(y + (size_t)i * 8u,               a);
    stg256_cs(y + ((size_t)i + QV8) * 8u,       b);
    stg256_cs(y + ((size_t)i + 2u * QV8) * 8u,  c);
    stg256_cs(y + ((size_t)i + 3u * QV8) * 8u,  e);
}

extern "C" void kernel_launch(void* const* d_in, const int* in_sizes, int n_in,
                              void* d_out, int out_size) {
    const float* x = (const float*)d_in[0];
    const float* W = (const float*)d_in[1];
    float* y = (float*)d_out;

    extract_diag_kernel<<<16, 256>>>(W);

    // QV8 threads, each doing 4 x v8: 1,048,576 / 256 = 4096 blocks.
    diag_scale_kernel<<<4096, 256>>>(x, y);
}